// round 5
// baseline (speedup 1.0000x reference)
#include <cuda_runtime.h>
#include <cstdint>

// Problem constants
#define B_ 16
#define K_ 49
#define T_ 256
#define H_ 512
#define D_ 512

// Output packing: (c_hat_t, alpha_t, beta_t) flattened in order
#define OUT_ALPHA (B_ * T_ * H_)              // 2097152
#define OUT_BETA  (OUT_ALPHA + B_ * T_ * K_)  // 2297856

// Scratch (device globals: allocation-free)
__device__ float g_cv[B_ * K_ * D_];   // V @ Wv + bv
__device__ float g_cg[B_ * T_ * D_];   // h_t @ Wg + bg
__device__ float g_cs[B_ * T_ * D_];   // s_t @ Ws + bs

// ---------------------------------------------------------------------------
// Merged TF32 mma.sync GEMM: computes all three C[M,512] = A[M,512]@W + bias.
// ---------------------------------------------------------------------------
__global__ __launch_bounds__(256)
void gemm3_tf32_kernel(const float* __restrict__ V, const float* __restrict__ h_t,
                       const float* __restrict__ s_t,
                       const float* __restrict__ Wv, const float* __restrict__ bv,
                       const float* __restrict__ Wg, const float* __restrict__ bg,
                       const float* __restrict__ Wss, const float* __restrict__ bss)
{
    __shared__ float As[128 * 32];     // [m][k], k index xor-swizzled by 4*(m&7)
    __shared__ float Bs[32 * 136];     // [k][n], row stride 136 (pad 8)

    const int nt = blockIdx.x;         // 0..3
    int mt = blockIdx.y;               // 0..70
    const float *A, *W, *bias;
    float* C;
    int M;
    if (mt < 7)       { A = V;   W = Wv;  bias = bv;  C = g_cv; M = B_ * K_; }
    else if (mt < 39) { A = h_t; W = Wg;  bias = bg;  C = g_cg; M = B_ * T_; mt -= 7; }
    else              { A = s_t; W = Wss; bias = bss; C = g_cs; M = B_ * T_; mt -= 39; }

    const int tid  = threadIdx.x;
    const int lane = tid & 31;
    const int wid  = tid >> 5;
    const int g    = lane >> 2;
    const int tg   = lane & 3;
    const int warp_m = (wid >> 2) * 64;
    const int warp_n = (wid & 3) * 32;

    const int mbase = mt * 128;
    const int nbase = nt * 128;

    float acc[4][4][4];
    #pragma unroll
    for (int i = 0; i < 4; i++)
        #pragma unroll
        for (int j = 0; j < 4; j++)
            #pragma unroll
            for (int q = 0; q < 4; q++) acc[i][j][q] = 0.f;

    const int a_m0 = tid >> 3;
    const int a_k4 = (tid & 7) * 4;
    const int w_k0 = tid >> 5;
    const int w_n4 = (tid & 31) * 4;

    float4 pa[4], pw[4];

    #pragma unroll
    for (int i = 0; i < 4; i++) {
        const int row = mbase + a_m0 + i * 32;
        pa[i] = (row < M) ? *reinterpret_cast<const float4*>(&A[(size_t)row * 512 + a_k4])
                          : make_float4(0.f, 0.f, 0.f, 0.f);
        pw[i] = *reinterpret_cast<const float4*>(&W[(size_t)(w_k0 + i * 8) * 512 + nbase + w_n4]);
    }
    #pragma unroll
    for (int i = 0; i < 4; i++) {
        const int m = a_m0 + i * 32;
        *reinterpret_cast<float4*>(&As[m * 32 + (a_k4 ^ (4 * (m & 7)))]) = pa[i];
        *reinterpret_cast<float4*>(&Bs[(w_k0 + i * 8) * 136 + w_n4]) = pw[i];
    }
    __syncthreads();

    const int sw = 4 * g;

    for (int kt = 0; kt < 512; kt += 32) {
        if (kt + 32 < 512) {
            #pragma unroll
            for (int i = 0; i < 4; i++) {
                const int row = mbase + a_m0 + i * 32;
                pa[i] = (row < M) ? *reinterpret_cast<const float4*>(&A[(size_t)row * 512 + kt + 32 + a_k4])
                                  : make_float4(0.f, 0.f, 0.f, 0.f);
                pw[i] = *reinterpret_cast<const float4*>(&W[(size_t)(kt + 32 + w_k0 + i * 8) * 512 + nbase + w_n4]);
            }
        }

        #pragma unroll
        for (int kb = 0; kb < 32; kb += 8) {
            uint32_t af[4][4], bf[4][2];
            #pragma unroll
            for (int mi = 0; mi < 4; mi++) {
                const int m0 = warp_m + mi * 16;
                const int k0 = (kb + tg) ^ sw;
                const int k1 = (kb + tg + 4) ^ sw;
                af[mi][0] = __float_as_uint(As[(m0 + g)     * 32 + k0]);
                af[mi][1] = __float_as_uint(As[(m0 + g + 8) * 32 + k0]);
                af[mi][2] = __float_as_uint(As[(m0 + g)     * 32 + k1]);
                af[mi][3] = __float_as_uint(As[(m0 + g + 8) * 32 + k1]);
            }
            #pragma unroll
            for (int ni = 0; ni < 4; ni++) {
                const int n_ = warp_n + ni * 8 + g;
                bf[ni][0] = __float_as_uint(Bs[(kb + tg)     * 136 + n_]);
                bf[ni][1] = __float_as_uint(Bs[(kb + tg + 4) * 136 + n_]);
            }
            #pragma unroll
            for (int mi = 0; mi < 4; mi++)
                #pragma unroll
                for (int ni = 0; ni < 4; ni++) {
                    asm volatile(
                        "mma.sync.aligned.m16n8k8.row.col.f32.tf32.tf32.f32 "
                        "{%0,%1,%2,%3}, {%4,%5,%6,%7}, {%8,%9}, {%0,%1,%2,%3};"
                        : "+f"(acc[mi][ni][0]), "+f"(acc[mi][ni][1]),
                          "+f"(acc[mi][ni][2]), "+f"(acc[mi][ni][3])
                        : "r"(af[mi][0]), "r"(af[mi][1]), "r"(af[mi][2]), "r"(af[mi][3]),
                          "r"(bf[ni][0]), "r"(bf[ni][1]));
                }
        }
        __syncthreads();
        if (kt + 32 < 512) {
            #pragma unroll
            for (int i = 0; i < 4; i++) {
                const int m = a_m0 + i * 32;
                *reinterpret_cast<float4*>(&As[m * 32 + (a_k4 ^ (4 * (m & 7)))]) = pa[i];
                *reinterpret_cast<float4*>(&Bs[(w_k0 + i * 8) * 136 + w_n4]) = pw[i];
            }
            __syncthreads();
        }
    }

    #pragma unroll
    for (int mi = 0; mi < 4; mi++) {
        const int r0 = mbase + warp_m + mi * 16 + g;
        const int r1 = r0 + 8;
        #pragma unroll
        for (int ni = 0; ni < 4; ni++) {
            const int c = nbase + warp_n + ni * 8 + tg * 2;
            const float2 bv2 = *reinterpret_cast<const float2*>(&bias[c]);
            if (r0 < M) {
                float2 o = make_float2(acc[mi][ni][0] + bv2.x, acc[mi][ni][1] + bv2.y);
                *reinterpret_cast<float2*>(&C[(size_t)r0 * 512 + c]) = o;
            }
            if (r1 < M) {
                float2 o = make_float2(acc[mi][ni][2] + bv2.x, acc[mi][ni][3] + bv2.y);
                *reinterpret_cast<float2*>(&C[(size_t)r1 * 512 + c]) = o;
            }
        }
    }
}

#define TWO_LOG2E 2.8853900817779268f

__device__ __forceinline__ float ex2a(float x)
{ float r; asm("ex2.approx.f32 %0, %1;" : "=f"(r) : "f"(x)); return r; }
__device__ __forceinline__ float rcpa(float x)
{ float r; asm("rcp.approx.f32 %0, %1;" : "=f"(r) : "f"(x)); return r; }

// 4 tanh values from 4 pre-scaled args m = 2*log2(e)*x, using 4 ex2 + ONE rcp.
// tanh(x) = 1 - 2/(2^m + 1). Batched reciprocal via product tree.
__device__ __forceinline__ void tanh4(const float4& m, float th[4])
{
    float p0 = ex2a(m.x) + 1.0f;
    float p1 = ex2a(m.y) + 1.0f;
    float p2 = ex2a(m.z) + 1.0f;
    float p3 = ex2a(m.w) + 1.0f;
    float t01 = p0 * p1;
    float t23 = p2 * p3;
    float R   = rcpa(t01 * t23);
    float R01 = R * t23;          // 1/(p0*p1)
    float R23 = R * t01;          // 1/(p2*p3)
    th[0] = fmaf(-2.0f, R01 * p1, 1.0f);
    th[1] = fmaf(-2.0f, R01 * p0, 1.0f);
    th[2] = fmaf(-2.0f, R23 * p3, 1.0f);
    th[3] = fmaf(-2.0f, R23 * p2, 1.0f);
}

// ---------------------------------------------------------------------------
// Fused kernel. Grid: B*(T/8)=512 blocks, 256 threads, warp w owns t=tile*8+w.
// Lane owns d in {128j + 4*lane + c}: coalesced float4 LDG, no smem staging,
// NO block barriers anywhere. k-loop unrolled by 2 for ILP.
// ---------------------------------------------------------------------------
__global__ __launch_bounds__(256, 3)
void fused_attn_kernel(const float* __restrict__ V, const float* __restrict__ s_t,
                       const float* __restrict__ Wh, const float* __restrict__ bh,
                       float* __restrict__ out)
{
    __shared__ float z_s[8][64];
    __shared__ float alpha_s[8][52];

    const int tid  = threadIdx.x;
    const int lane = tid & 31;
    const int w    = tid >> 5;
    const int b     = blockIdx.x >> 5;
    const int ttile = blockIdx.x & 31;
    const int t  = ttile * 8 + w;
    const int bt = b * T_ + t;

    // cg row (pre-scaled) and Wh: register-resident. d = 128j + 4*lane + c.
    float4 cg2[4], wh[4];
    {
        const float* __restrict__ cgrow = g_cg + (size_t)bt * 512 + lane * 4;
        const float* __restrict__ whrow = Wh + lane * 4;
        #pragma unroll
        for (int j = 0; j < 4; j++) {
            float4 a = *reinterpret_cast<const float4*>(&cgrow[j * 128]);
            a.x *= TWO_LOG2E; a.y *= TWO_LOG2E; a.z *= TWO_LOG2E; a.w *= TWO_LOG2E;
            cg2[j] = a;
            wh[j]  = *reinterpret_cast<const float4*>(&whrow[j * 128]);
        }
    }
    const float bhv = bh[0];

    const float* __restrict__ cvb = g_cv + (size_t)b * (K_ * 512) + lane * 4;

    // ---- z_t over k (pairs), direct LDG, no barriers ----
    #pragma unroll 1
    for (int k = 0; k < K_ - 1; k += 2) {
        float acc0 = 0.f, acc1 = 0.f;
        const float* __restrict__ r0 = cvb + (size_t)k * 512;
        const float* __restrict__ r1 = r0 + 512;
        #pragma unroll
        for (int j = 0; j < 4; j++) {
            float4 va = *reinterpret_cast<const float4*>(&r0[j * 128]);
            float4 vb = *reinterpret_cast<const float4*>(&r1[j * 128]);
            float4 ma, mb;
            ma.x = fmaf(va.x, TWO_LOG2E, cg2[j].x);
            ma.y = fmaf(va.y, TWO_LOG2E, cg2[j].y);
            ma.z = fmaf(va.z, TWO_LOG2E, cg2[j].z);
            ma.w = fmaf(va.w, TWO_LOG2E, cg2[j].w);
            mb.x = fmaf(vb.x, TWO_LOG2E, cg2[j].x);
            mb.y = fmaf(vb.y, TWO_LOG2E, cg2[j].y);
            mb.z = fmaf(vb.z, TWO_LOG2E, cg2[j].z);
            mb.w = fmaf(vb.w, TWO_LOG2E, cg2[j].w);
            float ta[4], tb[4];
            tanh4(ma, ta);
            tanh4(mb, tb);
            acc0 = fmaf(ta[0], wh[j].x, acc0);
            acc0 = fmaf(ta[1], wh[j].y, acc0);
            acc0 = fmaf(ta[2], wh[j].z, acc0);
            acc0 = fmaf(ta[3], wh[j].w, acc0);
            acc1 = fmaf(tb[0], wh[j].x, acc1);
            acc1 = fmaf(tb[1], wh[j].y, acc1);
            acc1 = fmaf(tb[2], wh[j].z, acc1);
            acc1 = fmaf(tb[3], wh[j].w, acc1);
        }
        #pragma unroll
        for (int o = 16; o > 0; o >>= 1) {
            acc0 += __shfl_xor_sync(0xffffffffu, acc0, o);
            acc1 += __shfl_xor_sync(0xffffffffu, acc1, o);
        }
        if (lane == 0) { z_s[w][k] = acc0 + bhv; z_s[w][k + 1] = acc1 + bhv; }
    }
    // tail k = 48
    {
        const int k = K_ - 1;
        float acc0 = 0.f;
        const float* __restrict__ r0 = cvb + (size_t)k * 512;
        #pragma unroll
        for (int j = 0; j < 4; j++) {
            float4 va = *reinterpret_cast<const float4*>(&r0[j * 128]);
            float4 ma;
            ma.x = fmaf(va.x, TWO_LOG2E, cg2[j].x);
            ma.y = fmaf(va.y, TWO_LOG2E, cg2[j].y);
            ma.z = fmaf(va.z, TWO_LOG2E, cg2[j].z);
            ma.w = fmaf(va.w, TWO_LOG2E, cg2[j].w);
            float ta[4];
            tanh4(ma, ta);
            acc0 = fmaf(ta[0], wh[j].x, acc0);
            acc0 = fmaf(ta[1], wh[j].y, acc0);
            acc0 = fmaf(ta[2], wh[j].z, acc0);
            acc0 = fmaf(ta[3], wh[j].w, acc0);
        }
        #pragma unroll
        for (int o = 16; o > 0; o >>= 1)
            acc0 += __shfl_xor_sync(0xffffffffu, acc0, o);
        if (lane == 0) z_s[w][k] = acc0 + bhv;
    }

    // ---- z_ext from content_s = cs_raw + cg ----
    {
        const float* __restrict__ csrow = g_cs + (size_t)bt * 512 + lane * 4;
        float acc = 0.f;
        #pragma unroll
        for (int j = 0; j < 4; j++) {
            float4 v = *reinterpret_cast<const float4*>(&csrow[j * 128]);
            float4 m;
            m.x = fmaf(v.x, TWO_LOG2E, cg2[j].x);
            m.y = fmaf(v.y, TWO_LOG2E, cg2[j].y);
            m.z = fmaf(v.z, TWO_LOG2E, cg2[j].z);
            m.w = fmaf(v.w, TWO_LOG2E, cg2[j].w);
            float tq[4];
            tanh4(m, tq);
            acc = fmaf(tq[0], wh[j].x, acc);
            acc = fmaf(tq[1], wh[j].y, acc);
            acc = fmaf(tq[2], wh[j].z, acc);
            acc = fmaf(tq[3], wh[j].w, acc);
        }
        #pragma unroll
        for (int o = 16; o > 0; o >>= 1)
            acc += __shfl_xor_sync(0xffffffffu, acc, o);
        if (lane == 0) z_s[w][K_] = acc + bhv;
    }
    __syncwarp();

    // ---- softmaxes: alpha over 49, beta from extended 50 (warp-local) ----
    float beta;
    {
        float z0 = (lane < K_)      ? z_s[w][lane]      : -1e30f;
        float z1 = (lane + 32 < K_) ? z_s[w][lane + 32] : -1e30f;
        float ze = z_s[w][K_];
        float m = fmaxf(fmaxf(z0, z1), ze);
        #pragma unroll
        for (int o = 16; o > 0; o >>= 1)
            m = fmaxf(m, __shfl_xor_sync(0xffffffffu, m, o));

        float e0 = (lane < K_)      ? __expf(z0 - m) : 0.f;
        float e1 = (lane + 32 < K_) ? __expf(z1 - m) : 0.f;
        float ee = __expf(ze - m);

        float s = e0 + e1;
        #pragma unroll
        for (int o = 16; o > 0; o >>= 1)
            s += __shfl_xor_sync(0xffffffffu, s, o);
        beta = ee / (s + ee);
        const float inv = 1.0f / s;

        if (lane < K_) {
            float a0 = e0 * inv;
            alpha_s[w][lane] = a0;
            out[OUT_ALPHA + (size_t)bt * K_ + lane] = a0;
        }
        if (lane + 32 < K_) {
            float a1 = e1 * inv;
            alpha_s[w][lane + 32] = a1;
            out[OUT_ALPHA + (size_t)bt * K_ + lane + 32] = a1;
        }
        if (lane == 0) out[OUT_BETA + bt] = beta;
    }
    __syncwarp();

    // ---- c_t = alpha @ V, direct LDG, no barriers ----
    float4 cacc[4];
    #pragma unroll
    for (int j = 0; j < 4; j++) cacc[j] = make_float4(0.f, 0.f, 0.f, 0.f);

    const float* __restrict__ Vb = V + (size_t)b * (K_ * 512) + lane * 4;
    #pragma unroll 1
    for (int k = 0; k < K_ - 1; k += 2) {
        const float a0 = alpha_s[w][k];
        const float a1 = alpha_s[w][k + 1];
        const float* __restrict__ r0 = Vb + (size_t)k * 512;
        const float* __restrict__ r1 = r0 + 512;
        #pragma unroll
        for (int j = 0; j < 4; j++) {
            float4 va = *reinterpret_cast<const float4*>(&r0[j * 128]);
            float4 vb = *reinterpret_cast<const float4*>(&r1[j * 128]);
            cacc[j].x = fmaf(a0, va.x, fmaf(a1, vb.x, cacc[j].x));
            cacc[j].y = fmaf(a0, va.y, fmaf(a1, vb.y, cacc[j].y));
            cacc[j].z = fmaf(a0, va.z, fmaf(a1, vb.z, cacc[j].z));
            cacc[j].w = fmaf(a0, va.w, fmaf(a1, vb.w, cacc[j].w));
        }
    }
    {
        const int k = K_ - 1;
        const float a0 = alpha_s[w][k];
        const float* __restrict__ r0 = Vb + (size_t)k * 512;
        #pragma unroll
        for (int j = 0; j < 4; j++) {
            float4 va = *reinterpret_cast<const float4*>(&r0[j * 128]);
            cacc[j].x = fmaf(a0, va.x, cacc[j].x);
            cacc[j].y = fmaf(a0, va.y, cacc[j].y);
            cacc[j].z = fmaf(a0, va.z, cacc[j].z);
            cacc[j].w = fmaf(a0, va.w, cacc[j].w);
        }
    }

    // ---- c_hat = c + beta*(s - c) ----
    {
        const float* __restrict__ srow = s_t + (size_t)bt * 512 + lane * 4;
        float* __restrict__ orow = out + (size_t)bt * 512 + lane * 4;
        #pragma unroll
        for (int j = 0; j < 4; j++) {
            float4 sv = *reinterpret_cast<const float4*>(&srow[j * 128]);
            float4 o;
            o.x = fmaf(beta, sv.x - cacc[j].x, cacc[j].x);
            o.y = fmaf(beta, sv.y - cacc[j].y, cacc[j].y);
            o.z = fmaf(beta, sv.z - cacc[j].z, cacc[j].z);
            o.w = fmaf(beta, sv.w - cacc[j].w, cacc[j].w);
            *reinterpret_cast<float4*>(&orow[j * 128]) = o;
        }
    }
}

// ---------------------------------------------------------------------------
extern "C" void kernel_launch(void* const* d_in, const int* in_sizes, int n_in,
                              void* d_out, int out_size)
{
    (void)in_sizes; (void)n_in; (void)out_size;
    const float* V   = (const float*)d_in[0];
    const float* h_t = (const float*)d_in[1];
    const float* s_t = (const float*)d_in[2];
    const float* Wv  = (const float*)d_in[3];
    const float* bv  = (const float*)d_in[4];
    const float* Wg  = (const float*)d_in[5];
    const float* bg  = (const float*)d_in[6];
    const float* Ws  = (const float*)d_in[7];
    const float* bs  = (const float*)d_in[8];
    const float* Wh  = (const float*)d_in[9];
    const float* bh  = (const float*)d_in[10];
    float* out = (float*)d_out;

    gemm3_tf32_kernel<<<dim3(4, 71), 256>>>(V, h_t, s_t, Wv, bv, Wg, bg, Ws, bs);
    fused_attn_kernel<<<dim3(B_ * (T_ / 8)), 256>>>(V, s_t, Wh, bh, out);
}

// round 7
// speedup vs baseline: 1.0818x; 1.0818x over previous
#include <cuda_runtime.h>
#include <cstdint>

// Problem constants
#define B_ 16
#define K_ 49
#define T_ 256
#define H_ 512
#define D_ 512

// Output packing: (c_hat_t, alpha_t, beta_t) flattened in order
#define OUT_ALPHA (B_ * T_ * H_)              // 2097152
#define OUT_BETA  (OUT_ALPHA + B_ * T_ * K_)  // 2297856

// Scratch (device globals: allocation-free)
__device__ float g_cv[B_ * K_ * D_];   // V @ Wv + bv
__device__ float g_cg[B_ * T_ * D_];   // h_t @ Wg + bg
__device__ float g_cs[B_ * T_ * D_];   // s_t @ Ws + bs

// ---------------------------------------------------------------------------
// Merged TF32 mma.sync GEMM: computes all three C[M,512] = A[M,512]@W + bias.
// ---------------------------------------------------------------------------
__global__ __launch_bounds__(256)
void gemm3_tf32_kernel(const float* __restrict__ V, const float* __restrict__ h_t,
                       const float* __restrict__ s_t,
                       const float* __restrict__ Wv, const float* __restrict__ bv,
                       const float* __restrict__ Wg, const float* __restrict__ bg,
                       const float* __restrict__ Wss, const float* __restrict__ bss)
{
    __shared__ float As[128 * 32];     // [m][k], k index xor-swizzled by 4*(m&7)
    __shared__ float Bs[32 * 136];     // [k][n], row stride 136 (pad 8)

    const int nt = blockIdx.x;         // 0..3
    int mt = blockIdx.y;               // 0..70
    const float *A, *W, *bias;
    float* C;
    int M;
    if (mt < 7)       { A = V;   W = Wv;  bias = bv;  C = g_cv; M = B_ * K_; }
    else if (mt < 39) { A = h_t; W = Wg;  bias = bg;  C = g_cg; M = B_ * T_; mt -= 7; }
    else              { A = s_t; W = Wss; bias = bss; C = g_cs; M = B_ * T_; mt -= 39; }

    const int tid  = threadIdx.x;
    const int lane = tid & 31;
    const int wid  = tid >> 5;
    const int g    = lane >> 2;
    const int tg   = lane & 3;
    const int warp_m = (wid >> 2) * 64;
    const int warp_n = (wid & 3) * 32;

    const int mbase = mt * 128;
    const int nbase = nt * 128;

    float acc[4][4][4];
    #pragma unroll
    for (int i = 0; i < 4; i++)
        #pragma unroll
        for (int j = 0; j < 4; j++)
            #pragma unroll
            for (int q = 0; q < 4; q++) acc[i][j][q] = 0.f;

    const int a_m0 = tid >> 3;
    const int a_k4 = (tid & 7) * 4;
    const int w_k0 = tid >> 5;
    const int w_n4 = (tid & 31) * 4;

    float4 pa[4], pw[4];

    #pragma unroll
    for (int i = 0; i < 4; i++) {
        const int row = mbase + a_m0 + i * 32;
        pa[i] = (row < M) ? *reinterpret_cast<const float4*>(&A[(size_t)row * 512 + a_k4])
                          : make_float4(0.f, 0.f, 0.f, 0.f);
        pw[i] = *reinterpret_cast<const float4*>(&W[(size_t)(w_k0 + i * 8) * 512 + nbase + w_n4]);
    }
    #pragma unroll
    for (int i = 0; i < 4; i++) {
        const int m = a_m0 + i * 32;
        *reinterpret_cast<float4*>(&As[m * 32 + (a_k4 ^ (4 * (m & 7)))]) = pa[i];
        *reinterpret_cast<float4*>(&Bs[(w_k0 + i * 8) * 136 + w_n4]) = pw[i];
    }
    __syncthreads();

    const int sw = 4 * g;

    for (int kt = 0; kt < 512; kt += 32) {
        if (kt + 32 < 512) {
            #pragma unroll
            for (int i = 0; i < 4; i++) {
                const int row = mbase + a_m0 + i * 32;
                pa[i] = (row < M) ? *reinterpret_cast<const float4*>(&A[(size_t)row * 512 + kt + 32 + a_k4])
                                  : make_float4(0.f, 0.f, 0.f, 0.f);
                pw[i] = *reinterpret_cast<const float4*>(&W[(size_t)(kt + 32 + w_k0 + i * 8) * 512 + nbase + w_n4]);
            }
        }

        #pragma unroll
        for (int kb = 0; kb < 32; kb += 8) {
            uint32_t af[4][4], bf[4][2];
            #pragma unroll
            for (int mi = 0; mi < 4; mi++) {
                const int m0 = warp_m + mi * 16;
                const int k0 = (kb + tg) ^ sw;
                const int k1 = (kb + tg + 4) ^ sw;
                af[mi][0] = __float_as_uint(As[(m0 + g)     * 32 + k0]);
                af[mi][1] = __float_as_uint(As[(m0 + g + 8) * 32 + k0]);
                af[mi][2] = __float_as_uint(As[(m0 + g)     * 32 + k1]);
                af[mi][3] = __float_as_uint(As[(m0 + g + 8) * 32 + k1]);
            }
            #pragma unroll
            for (int ni = 0; ni < 4; ni++) {
                const int n_ = warp_n + ni * 8 + g;
                bf[ni][0] = __float_as_uint(Bs[(kb + tg)     * 136 + n_]);
                bf[ni][1] = __float_as_uint(Bs[(kb + tg + 4) * 136 + n_]);
            }
            #pragma unroll
            for (int mi = 0; mi < 4; mi++)
                #pragma unroll
                for (int ni = 0; ni < 4; ni++) {
                    asm volatile(
                        "mma.sync.aligned.m16n8k8.row.col.f32.tf32.tf32.f32 "
                        "{%0,%1,%2,%3}, {%4,%5,%6,%7}, {%8,%9}, {%0,%1,%2,%3};"
                        : "+f"(acc[mi][ni][0]), "+f"(acc[mi][ni][1]),
                          "+f"(acc[mi][ni][2]), "+f"(acc[mi][ni][3])
                        : "r"(af[mi][0]), "r"(af[mi][1]), "r"(af[mi][2]), "r"(af[mi][3]),
                          "r"(bf[ni][0]), "r"(bf[ni][1]));
                }
        }
        __syncthreads();
        if (kt + 32 < 512) {
            #pragma unroll
            for (int i = 0; i < 4; i++) {
                const int m = a_m0 + i * 32;
                *reinterpret_cast<float4*>(&As[m * 32 + (a_k4 ^ (4 * (m & 7)))]) = pa[i];
                *reinterpret_cast<float4*>(&Bs[(w_k0 + i * 8) * 136 + w_n4]) = pw[i];
            }
            __syncthreads();
        }
    }

    #pragma unroll
    for (int mi = 0; mi < 4; mi++) {
        const int r0 = mbase + warp_m + mi * 16 + g;
        const int r1 = r0 + 8;
        #pragma unroll
        for (int ni = 0; ni < 4; ni++) {
            const int c = nbase + warp_n + ni * 8 + tg * 2;
            const float2 bv2 = *reinterpret_cast<const float2*>(&bias[c]);
            if (r0 < M) {
                float2 o = make_float2(acc[mi][ni][0] + bv2.x, acc[mi][ni][1] + bv2.y);
                *reinterpret_cast<float2*>(&C[(size_t)r0 * 512 + c]) = o;
            }
            if (r1 < M) {
                float2 o = make_float2(acc[mi][ni][2] + bv2.x, acc[mi][ni][3] + bv2.y);
                *reinterpret_cast<float2*>(&C[(size_t)r1 * 512 + c]) = o;
            }
        }
    }
}

#define TWO_LOG2E 2.8853900817779268f

__device__ __forceinline__ float ex2a(float x)
{ float r; asm("ex2.approx.f32 %0, %1;" : "=f"(r) : "f"(x)); return r; }
__device__ __forceinline__ float rcpa(float x)
{ float r; asm("rcp.approx.f32 %0, %1;" : "=f"(r) : "f"(x)); return r; }

// 4 tanh values from 4 pre-scaled args m = 2*log2(e)*x, using 4 ex2 + ONE rcp.
__device__ __forceinline__ void tanh4(const float4& m, float th[4])
{
    float p0 = ex2a(m.x) + 1.0f;
    float p1 = ex2a(m.y) + 1.0f;
    float p2 = ex2a(m.z) + 1.0f;
    float p3 = ex2a(m.w) + 1.0f;
    float t01 = p0 * p1;
    float t23 = p2 * p3;
    float R   = rcpa(t01 * t23);
    float R01 = R * t23;
    float R23 = R * t01;
    th[0] = fmaf(-2.0f, R01 * p1, 1.0f);
    th[1] = fmaf(-2.0f, R01 * p0, 1.0f);
    th[2] = fmaf(-2.0f, R23 * p3, 1.0f);
    th[3] = fmaf(-2.0f, R23 * p2, 1.0f);
}

// One z-row: acc += sum_d tanh(row[d] + cg[d]) * Wh[d], lane-partial form.
__device__ __forceinline__ float z_row(const float* __restrict__ r,
                                       const float4 cg2[4], const float4 wh[4])
{
    float acc = 0.f;
    #pragma unroll
    for (int j = 0; j < 4; j++) {
        float4 v = *reinterpret_cast<const float4*>(&r[j * 128]);
        float4 m;
        m.x = fmaf(v.x, TWO_LOG2E, cg2[j].x);
        m.y = fmaf(v.y, TWO_LOG2E, cg2[j].y);
        m.z = fmaf(v.z, TWO_LOG2E, cg2[j].z);
        m.w = fmaf(v.w, TWO_LOG2E, cg2[j].w);
        float tq[4];
        tanh4(m, tq);
        acc = fmaf(tq[0], wh[j].x, acc);
        acc = fmaf(tq[1], wh[j].y, acc);
        acc = fmaf(tq[2], wh[j].z, acc);
        acc = fmaf(tq[3], wh[j].w, acc);
    }
    return acc;
}

// ---------------------------------------------------------------------------
// Fused kernel, one CTA per (b,t): grid = B*T = 4096, 128 threads (4 warps).
// Warps split the k-range (stride-4). Warp 3 adds z_ext; warp 0 does softmax.
// c_t accumulated as 4 per-warp partials, combined in smem.
// NOTE: part[] declared FIRST and align(16) — float4 access requires it.
// ---------------------------------------------------------------------------
__global__ __launch_bounds__(128, 6)
void fused_attn_kernel(const float* __restrict__ V, const float* __restrict__ s_t,
                       const float* __restrict__ Wh, const float* __restrict__ bh,
                       float* __restrict__ out)
{
    __shared__ __align__(16) float part[4][512];
    __shared__ float z_s[52];
    __shared__ float alpha_s[52];
    __shared__ float beta_sh;

    const int tid  = threadIdx.x;
    const int lane = tid & 31;
    const int w    = tid >> 5;
    const int bt = blockIdx.x;
    const int b  = bt >> 8;            // bt / T_

    // cg row (pre-scaled) and Wh: register-resident. d = 128j + 4*lane + c.
    float4 cg2[4], wh[4];
    {
        const float* __restrict__ cgrow = g_cg + (size_t)bt * 512 + lane * 4;
        const float* __restrict__ whrow = Wh + lane * 4;
        #pragma unroll
        for (int j = 0; j < 4; j++) {
            float4 a = *reinterpret_cast<const float4*>(&cgrow[j * 128]);
            a.x *= TWO_LOG2E; a.y *= TWO_LOG2E; a.z *= TWO_LOG2E; a.w *= TWO_LOG2E;
            cg2[j] = a;
            wh[j]  = *reinterpret_cast<const float4*>(&whrow[j * 128]);
        }
    }
    const float bhv = bh[0];

    const float* __restrict__ cvb = g_cv + (size_t)b * (K_ * 512) + lane * 4;

    // ---- z over this warp's k-subset: k = w, w+4, w+8, ... ----
    const int n = (K_ - w + 3) >> 2;   // 13,12,12,12
    int i = 0;
    for (; i + 1 < n; i += 2) {
        const int k0 = w + 4 * i;
        const int k1 = k0 + 4;
        float a0 = z_row(cvb + (size_t)k0 * 512, cg2, wh);
        float a1 = z_row(cvb + (size_t)k1 * 512, cg2, wh);
        #pragma unroll
        for (int o = 16; o > 0; o >>= 1) {
            a0 += __shfl_xor_sync(0xffffffffu, a0, o);
            a1 += __shfl_xor_sync(0xffffffffu, a1, o);
        }
        if (lane == 0) { z_s[k0] = a0 + bhv; z_s[k1] = a1 + bhv; }
    }
    if (i < n) {
        const int k0 = w + 4 * i;
        float a0 = z_row(cvb + (size_t)k0 * 512, cg2, wh);
        #pragma unroll
        for (int o = 16; o > 0; o >>= 1)
            a0 += __shfl_xor_sync(0xffffffffu, a0, o);
        if (lane == 0) z_s[k0] = a0 + bhv;
    }

    // ---- z_ext (warp 3): content_s = cs_raw + cg ----
    if (w == 3) {
        float acc = z_row(g_cs + (size_t)bt * 512 + lane * 4, cg2, wh);
        #pragma unroll
        for (int o = 16; o > 0; o >>= 1)
            acc += __shfl_xor_sync(0xffffffffu, acc, o);
        if (lane == 0) z_s[K_] = acc + bhv;
    }
    __syncthreads();

    // ---- softmaxes (warp 0): alpha over 49, beta from extended 50 ----
    if (w == 0) {
        float z0 = (lane < K_)      ? z_s[lane]      : -1e30f;
        float z1 = (lane + 32 < K_) ? z_s[lane + 32] : -1e30f;
        float ze = z_s[K_];
        float m = fmaxf(fmaxf(z0, z1), ze);
        #pragma unroll
        for (int o = 16; o > 0; o >>= 1)
            m = fmaxf(m, __shfl_xor_sync(0xffffffffu, m, o));

        float e0 = (lane < K_)      ? __expf(z0 - m) : 0.f;
        float e1 = (lane + 32 < K_) ? __expf(z1 - m) : 0.f;
        float ee = __expf(ze - m);

        float s = e0 + e1;
        #pragma unroll
        for (int o = 16; o > 0; o >>= 1)
            s += __shfl_xor_sync(0xffffffffu, s, o);
        const float beta = ee / (s + ee);
        const float inv = 1.0f / s;

        if (lane < K_) {
            float a0 = e0 * inv;
            alpha_s[lane] = a0;
            out[OUT_ALPHA + (size_t)bt * K_ + lane] = a0;
        }
        if (lane + 32 < K_) {
            float a1 = e1 * inv;
            alpha_s[lane + 32] = a1;
            out[OUT_ALPHA + (size_t)bt * K_ + lane + 32] = a1;
        }
        if (lane == 0) {
            beta_sh = beta;
            out[OUT_BETA + bt] = beta;
        }
    }
    __syncthreads();

    // ---- c_t partial over this warp's k-subset ----
    float4 cacc[4];
    #pragma unroll
    for (int j = 0; j < 4; j++) cacc[j] = make_float4(0.f, 0.f, 0.f, 0.f);

    const float* __restrict__ Vb = V + (size_t)b * (K_ * 512) + lane * 4;
    i = 0;
    for (; i + 1 < n; i += 2) {
        const int k0 = w + 4 * i;
        const int k1 = k0 + 4;
        const float a0 = alpha_s[k0];
        const float a1 = alpha_s[k1];
        const float* __restrict__ r0 = Vb + (size_t)k0 * 512;
        const float* __restrict__ r1 = Vb + (size_t)k1 * 512;
        #pragma unroll
        for (int j = 0; j < 4; j++) {
            float4 va = *reinterpret_cast<const float4*>(&r0[j * 128]);
            float4 vb = *reinterpret_cast<const float4*>(&r1[j * 128]);
            cacc[j].x = fmaf(a0, va.x, fmaf(a1, vb.x, cacc[j].x));
            cacc[j].y = fmaf(a0, va.y, fmaf(a1, vb.y, cacc[j].y));
            cacc[j].z = fmaf(a0, va.z, fmaf(a1, vb.z, cacc[j].z));
            cacc[j].w = fmaf(a0, va.w, fmaf(a1, vb.w, cacc[j].w));
        }
    }
    if (i < n) {
        const int k0 = w + 4 * i;
        const float a0 = alpha_s[k0];
        const float* __restrict__ r0 = Vb + (size_t)k0 * 512;
        #pragma unroll
        for (int j = 0; j < 4; j++) {
            float4 va = *reinterpret_cast<const float4*>(&r0[j * 128]);
            cacc[j].x = fmaf(a0, va.x, cacc[j].x);
            cacc[j].y = fmaf(a0, va.y, cacc[j].y);
            cacc[j].z = fmaf(a0, va.z, cacc[j].z);
            cacc[j].w = fmaf(a0, va.w, cacc[j].w);
        }
    }
    #pragma unroll
    for (int j = 0; j < 4; j++)
        *reinterpret_cast<float4*>(&part[w][j * 128 + lane * 4]) = cacc[j];
    __syncthreads();

    // ---- combine partials + blend: thread owns d in [4*tid, 4*tid+4) ----
    {
        const float beta = beta_sh;
        const int d = tid * 4;
        float4 p0 = *reinterpret_cast<const float4*>(&part[0][d]);
        float4 p1 = *reinterpret_cast<const float4*>(&part[1][d]);
        float4 p2 = *reinterpret_cast<const float4*>(&part[2][d]);
        float4 p3 = *reinterpret_cast<const float4*>(&part[3][d]);
        float4 c;
        c.x = (p0.x + p1.x) + (p2.x + p3.x);
        c.y = (p0.y + p1.y) + (p2.y + p3.y);
        c.z = (p0.z + p1.z) + (p2.z + p3.z);
        c.w = (p0.w + p1.w) + (p2.w + p3.w);
        float4 sv = *reinterpret_cast<const float4*>(&s_t[(size_t)bt * 512 + d]);
        float4 o;
        o.x = fmaf(beta, sv.x - c.x, c.x);
        o.y = fmaf(beta, sv.y - c.y, c.y);
        o.z = fmaf(beta, sv.z - c.z, c.z);
        o.w = fmaf(beta, sv.w - c.w, c.w);
        *reinterpret_cast<float4*>(&out[(size_t)bt * 512 + d]) = o;
    }
}

// ---------------------------------------------------------------------------
extern "C" void kernel_launch(void* const* d_in, const int* in_sizes, int n_in,
                              void* d_out, int out_size)
{
    (void)in_sizes; (void)n_in; (void)out_size;
    const float* V   = (const float*)d_in[0];
    const float* h_t = (const float*)d_in[1];
    const float* s_t = (const float*)d_in[2];
    const float* Wv  = (const float*)d_in[3];
    const float* bv  = (const float*)d_in[4];
    const float* Wg  = (const float*)d_in[5];
    const float* bg  = (const float*)d_in[6];
    const float* Ws  = (const float*)d_in[7];
    const float* bs  = (const float*)d_in[8];
    const float* Wh  = (const float*)d_in[9];
    const float* bh  = (const float*)d_in[10];
    float* out = (float*)d_out;

    gemm3_tf32_kernel<<<dim3(4, 71), 256>>>(V, h_t, s_t, Wv, bv, Wg, bg, Ws, bs);
    fused_attn_kernel<<<dim3(B_ * T_), 128>>>(V, s_t, Wh, bh, out);
}